// round 3
// baseline (speedup 1.0000x reference)
#include <cuda_runtime.h>
#include <cstdint>

#define NMAX 50000
#define EMAX 600000
#define HID 128
#define INDIM 256
#define BN_EPS 1e-5f
#define SCAN_BLK 256

// ---------------- scratch (no allocations allowed) ----------------
__device__ float g_h[(size_t)NMAX * HID];   // x @ W
__device__ int   g_degE[NMAX];              // in-degree (edges only)
__device__ int   g_scan[NMAX];              // per-block inclusive scan
__device__ int   g_rowptr[NMAX];            // CSR row offsets (exclusive)
__device__ int   g_cursor[NMAX];            // fill cursors
__device__ int   g_bsum[SCAN_BLK];          // block sums for scan
__device__ int   g_csr_src[EMAX];           // source node per CSR slot
__device__ float g_dinv[NMAX];
__device__ float g_sum[HID];
__device__ float g_sumsq[HID];
__device__ float g_scale[HID];
__device__ float g_shift[HID];

// ---------------- K0: zero all per-run state ----------------
__global__ void k_init(int N) {
    int i = blockIdx.x * blockDim.x + threadIdx.x;
    if (i < N) { g_degE[i] = 0; g_cursor[i] = 0; }
    if (i < HID) { g_sum[i] = 0.0f; g_sumsq[i] = 0.0f; }
    if (i < SCAN_BLK) g_bsum[i] = 0;
}

// ---------------- K1: sgemm h = x @ W  (M x 256) @ (256 x 128) ----------------
__global__ __launch_bounds__(256, 2)
void k_gemm(const float* __restrict__ x, const float* __restrict__ W, int M) {
    __shared__ float XsT[16][128];   // transposed x tile: [k][row]
    __shared__ float Ws[16][128];    // [k][col]

    const int tid = threadIdx.x;
    const int m0  = blockIdx.x * 128;
    const int tx  = tid & 15;        // col group
    const int ty  = tid >> 4;        // row group

    float acc[8][8];
    #pragma unroll
    for (int i = 0; i < 8; i++)
        #pragma unroll
        for (int j = 0; j < 8; j++) acc[i][j] = 0.0f;

    for (int k0 = 0; k0 < INDIM; k0 += 16) {
        #pragma unroll
        for (int i = 0; i < 2; i++) {
            int s  = tid + i * 256;
            int r  = s >> 2;
            int cv = s & 3;
            float4 v = make_float4(0.f, 0.f, 0.f, 0.f);
            int gm = m0 + r;
            if (gm < M)
                v = *(const float4*)(x + (size_t)gm * INDIM + k0 + cv * 4);
            XsT[cv * 4 + 0][r] = v.x;
            XsT[cv * 4 + 1][r] = v.y;
            XsT[cv * 4 + 2][r] = v.z;
            XsT[cv * 4 + 3][r] = v.w;
        }
        #pragma unroll
        for (int i = 0; i < 2; i++) {
            int s  = tid + i * 256;
            int r  = s >> 5;
            int cv = s & 31;
            float4 v = *(const float4*)(W + (size_t)(k0 + r) * HID + cv * 4);
            *(float4*)(&Ws[r][cv * 4]) = v;
        }
        __syncthreads();

        #pragma unroll
        for (int k = 0; k < 16; k++) {
            float a[8], b[8];
            *(float4*)(a)     = *(const float4*)(&XsT[k][ty * 8]);
            *(float4*)(a + 4) = *(const float4*)(&XsT[k][ty * 8 + 4]);
            *(float4*)(b)     = *(const float4*)(&Ws[k][tx * 8]);
            *(float4*)(b + 4) = *(const float4*)(&Ws[k][tx * 8 + 4]);
            #pragma unroll
            for (int i = 0; i < 8; i++)
                #pragma unroll
                for (int j = 0; j < 8; j++)
                    acc[i][j] += a[i] * b[j];
        }
        __syncthreads();
    }

    #pragma unroll
    for (int i = 0; i < 8; i++) {
        int gm = m0 + ty * 8 + i;
        if (gm < M) {
            #pragma unroll
            for (int jv = 0; jv < 2; jv++) {
                float4 v = make_float4(acc[i][jv * 4 + 0], acc[i][jv * 4 + 1],
                                       acc[i][jv * 4 + 2], acc[i][jv * 4 + 3]);
                *(float4*)(g_h + (size_t)gm * HID + tx * 8 + jv * 4) = v;
            }
        }
    }
}

// ---------------- K2: in-degree on targets (int atomics) ----------------
__global__ void k_deg(const int* __restrict__ ei, int E) {
    int e = blockIdx.x * blockDim.x + threadIdx.x;
    if (e < E) {
        int c = ei[E + e];
        atomicAdd(&g_degE[c], 1);
    }
}

// ---------------- K3a: per-block inclusive scan of degE ----------------
__global__ void k_scan1(int N) {
    __shared__ int sh[SCAN_BLK];
    int i = blockIdx.x * SCAN_BLK + threadIdx.x;
    int v = (i < N) ? g_degE[i] : 0;
    sh[threadIdx.x] = v;
    __syncthreads();
    #pragma unroll
    for (int off = 1; off < SCAN_BLK; off <<= 1) {
        int t = (threadIdx.x >= off) ? sh[threadIdx.x - off] : 0;
        __syncthreads();
        sh[threadIdx.x] += t;
        __syncthreads();
    }
    if (i < N) g_scan[i] = sh[threadIdx.x];
    if (threadIdx.x == SCAN_BLK - 1) g_bsum[blockIdx.x] = sh[SCAN_BLK - 1];
}

// ---------------- K3b: inclusive scan of block sums (single block) ----------------
__global__ void k_scan2(int nblk) {
    __shared__ int sh[SCAN_BLK];
    int v = (threadIdx.x < nblk) ? g_bsum[threadIdx.x] : 0;
    sh[threadIdx.x] = v;
    __syncthreads();
    #pragma unroll
    for (int off = 1; off < SCAN_BLK; off <<= 1) {
        int t = (threadIdx.x >= off) ? sh[threadIdx.x - off] : 0;
        __syncthreads();
        sh[threadIdx.x] += t;
        __syncthreads();
    }
    g_bsum[threadIdx.x] = sh[threadIdx.x];
}

// ---------------- K3c: rowptr (exclusive) + dinv ----------------
__global__ void k_scan3(int N) {
    int i = blockIdx.x * SCAN_BLK + threadIdx.x;
    if (i >= N) return;
    int base = (blockIdx.x > 0) ? g_bsum[blockIdx.x - 1] : 0;
    g_rowptr[i] = base + g_scan[i] - g_degE[i];
    g_dinv[i]   = rsqrtf((float)(g_degE[i] + 1));   // +1 self-loop
}

// ---------------- K4: fill CSR source list ----------------
__global__ void k_fill(const int* __restrict__ ei, int E) {
    int e = blockIdx.x * blockDim.x + threadIdx.x;
    if (e >= E) return;
    int r = ei[e];
    int c = ei[E + e];
    int pos = atomicAdd(&g_cursor[c], 1);
    g_csr_src[g_rowptr[c] + pos] = r;
}

// ---------------- K5: gather-reduce, one warp per node ----------------
__global__ void k_gather(float* __restrict__ out, int N) {
    int g    = blockIdx.x * blockDim.x + threadIdx.x;
    int node = g >> 5;
    int lane = g & 31;
    if (node >= N) return;

    float di = g_dinv[node];
    // self-loop contribution: h[node] * dinv^2
    float4 acc = ((const float4*)(g_h + (size_t)node * HID))[lane];
    float n2 = di * di;
    acc.x *= n2; acc.y *= n2; acc.z *= n2; acc.w *= n2;

    int s  = g_rowptr[node];
    int e2 = s + g_degE[node];
    for (int j = s; j < e2; j++) {
        int   r  = g_csr_src[j];
        float nr = di * g_dinv[r];
        float4 v = ((const float4*)(g_h + (size_t)r * HID))[lane];
        acc.x = fmaf(v.x, nr, acc.x);
        acc.y = fmaf(v.y, nr, acc.y);
        acc.z = fmaf(v.z, nr, acc.z);
        acc.w = fmaf(v.w, nr, acc.w);
    }
    ((float4*)(out + (size_t)node * HID))[lane] = acc;
}

// ---------------- K6: per-channel sum / sumsq ----------------
__global__ void k_colstat(const float* __restrict__ out, int N) {
    int ch  = threadIdx.x & 127;
    int sub = threadIdx.x >> 7;     // 0..3 (512 threads)
    float s = 0.f, s2 = 0.f;
    for (int r = blockIdx.x * 4 + sub; r < N; r += gridDim.x * 4) {
        float v = out[(size_t)r * HID + ch];
        s += v; s2 += v * v;
    }
    __shared__ float sh[4][HID];
    __shared__ float sh2[4][HID];
    sh[sub][ch] = s; sh2[sub][ch] = s2;
    __syncthreads();
    if (sub == 0) {
        float ts = sh[0][ch] + sh[1][ch] + sh[2][ch] + sh[3][ch];
        float t2 = sh2[0][ch] + sh2[1][ch] + sh2[2][ch] + sh2[3][ch];
        atomicAdd(&g_sum[ch], ts);
        atomicAdd(&g_sumsq[ch], t2);
    }
}

// ---------------- K7: BN scale/shift (GCN bias b cancels inside BN) ----------------
__global__ void k_bnparam(int N, const float* __restrict__ gamma, const float* __restrict__ beta) {
    int c = threadIdx.x;
    float invN = 1.0f / (float)N;
    float mean = g_sum[c] * invN;
    float var  = g_sumsq[c] * invN - mean * mean;
    float sc   = gamma[c] * rsqrtf(var + BN_EPS);
    g_scale[c] = sc;
    g_shift[c] = beta[c] - mean * sc;
}

// ---------------- K8: y = relu(out*scale + shift), in place ----------------
__global__ void k_bnrelu(float* __restrict__ out, int total4) {
    int i = blockIdx.x * blockDim.x + threadIdx.x;
    if (i >= total4) return;
    float4 v  = ((const float4*)out)[i];
    int ch4   = i & 31;
    float4 sc = ((const float4*)g_scale)[ch4];
    float4 sh = ((const float4*)g_shift)[ch4];
    v.x = fmaxf(fmaf(v.x, sc.x, sh.x), 0.f);
    v.y = fmaxf(fmaf(v.y, sc.y, sh.y), 0.f);
    v.z = fmaxf(fmaf(v.z, sc.z, sh.z), 0.f);
    v.w = fmaxf(fmaf(v.w, sc.w, sh.w), 0.f);
    ((float4*)out)[i] = v;
}

// ---------------- launch ----------------
extern "C" void kernel_launch(void* const* d_in, const int* in_sizes, int n_in,
                              void* d_out, int out_size) {
    const float* x     = (const float*)d_in[0];
    const int*   ei    = (const int*)d_in[1];     // int32 (JAX x64 disabled)
    const float* W     = (const float*)d_in[2];
    // d_in[3] = b : cancels inside BatchNorm, unused
    const float* gamma = (const float*)d_in[4];
    const float* beta  = (const float*)d_in[5];
    float*       out   = (float*)d_out;

    const int N = in_sizes[0] / INDIM;     // 50000
    const int E = in_sizes[1] / 2;         // 600000
    const int nblk = (N + SCAN_BLK - 1) / SCAN_BLK;   // 196

    k_init<<<nblk, SCAN_BLK>>>(N);
    k_gemm<<<(N + 127) / 128, 256>>>(x, W, N);
    k_deg<<<(E + 255) / 256, 256>>>(ei, E);
    k_scan1<<<nblk, SCAN_BLK>>>(N);
    k_scan2<<<1, SCAN_BLK>>>(nblk);
    k_scan3<<<nblk, SCAN_BLK>>>(N);
    k_fill<<<(E + 255) / 256, 256>>>(ei, E);
    k_gather<<<(N * 32 + 255) / 256, 256>>>(out, N);
    k_colstat<<<512, 512>>>(out, N);
    k_bnparam<<<1, HID>>>(N, gamma, beta);
    k_bnrelu<<<(N * 32 + 255) / 256, 256>>>(out, N * 32);
}

// round 5
// speedup vs baseline: 1.4635x; 1.4635x over previous
#include <cuda_runtime.h>
#include <cuda_bf16.h>
#include <cstdint>

#define NMAX 50000
#define EMAX 600000
#define HID 128
#define INDIM 256
#define BN_EPS 1e-5f
#define SCAN_BLK 256

// ---------------- scratch (no allocations allowed) ----------------
__device__ float g_h[(size_t)NMAX * HID];         // x @ W
__device__ __nv_bfloat16 g_wt_hi[HID * INDIM];    // W^T split hi: [n][k]
__device__ __nv_bfloat16 g_wt_lo[HID * INDIM];    // W^T split lo: [n][k]
__device__ int   g_degE[NMAX];
__device__ int   g_scan[NMAX];
__device__ int   g_rowptr[NMAX];
__device__ int   g_cursor[NMAX];
__device__ int   g_bsum[SCAN_BLK];
__device__ int   g_csr_src[EMAX];
__device__ float g_dinv[NMAX];
__device__ float g_sum[HID];
__device__ float g_sumsq[HID];
__device__ float g_scale[HID];
__device__ float g_shift[HID];

// ---------------- K0: zero all per-run state ----------------
__global__ void k_init(int N) {
    int i = blockIdx.x * blockDim.x + threadIdx.x;
    if (i < N) { g_degE[i] = 0; g_cursor[i] = 0; }
    if (i < HID) { g_sum[i] = 0.0f; g_sumsq[i] = 0.0f; }
    if (i < SCAN_BLK) g_bsum[i] = 0;
}

// ---------------- Kw: transpose + bf16-split W -> g_wt_hi/lo [n][k] ----------------
__global__ void k_wsplit(const float* __restrict__ W) {
    int n = blockIdx.x;
    for (int k = threadIdx.x; k < INDIM; k += blockDim.x) {
        float f = W[(size_t)k * HID + n];
        __nv_bfloat16 h = __float2bfloat16(f);
        float r = f - __bfloat162float(h);
        g_wt_hi[n * INDIM + k] = h;
        g_wt_lo[n * INDIM + k] = __float2bfloat16(r);
    }
}

// ================= K1: HMMA GEMM  h = x @ W  via bf16-split =================
// mma.sync m16n8k16 bf16 (portable PTX, no 'a'-arch features).
// CTA: 128x128 tile, K-chunk 64. smem planes pitch 72 bf16 (144B) -> conflict-free.
#define PITCH 72
#define PLANE (128 * PITCH * 2)          // bytes per plane = 18432
#define SA_HI 0
#define SA_LO (PLANE)
#define SB_HI (2 * PLANE)
#define SB_LO (3 * PLANE)
#define SM_GEMM (4 * PLANE)              // 73728 B

__device__ __forceinline__ void mma16816(float c[4], uint32_t a0, uint32_t a1,
                                         uint32_t a2, uint32_t a3,
                                         uint32_t b0, uint32_t b1) {
    asm volatile("mma.sync.aligned.m16n8k16.row.col.f32.bf16.bf16.f32 "
                 "{%0,%1,%2,%3},{%4,%5,%6,%7},{%8,%9},{%0,%1,%2,%3};"
                 : "+f"(c[0]), "+f"(c[1]), "+f"(c[2]), "+f"(c[3])
                 : "r"(a0), "r"(a1), "r"(a2), "r"(a3), "r"(b0), "r"(b1));
}

__global__ __launch_bounds__(256, 1)
void k_gemm_mma(const float* __restrict__ x, int M) {
    extern __shared__ char smem[];
    const int tid  = threadIdx.x;
    const int wid  = tid >> 5;
    const int lane = tid & 31;
    const int m0   = blockIdx.x * 128;

    const int wm = wid & 3;         // 4 M-subtiles of 32
    const int wn = wid >> 2;        // 2 N-subtiles of 64

    float c[2][8][4];
    #pragma unroll
    for (int mf = 0; mf < 2; mf++)
        #pragma unroll
        for (int nf = 0; nf < 8; nf++)
            #pragma unroll
            for (int q = 0; q < 4; q++) c[mf][nf][q] = 0.0f;

    const int srow = tid >> 1;          // 0..127 (loader row)
    const int half = tid & 1;           // 32-col half of the 64-wide chunk
    const bool arow_ok = (m0 + srow) < M;

    const int groupID = lane >> 2;
    const int tq      = lane & 3;

    #pragma unroll 1
    for (int ch = 0; ch < INDIM / 64; ch++) {
        const int k0 = ch * 64;
        __syncthreads();

        // ---- stage A: x fp32 -> bf16 hi/lo (row srow, cols half*32..+32) ----
        {
            const float4* src = (const float4*)(x + (size_t)(m0 + srow) * INDIM + k0 + half * 32);
            char* ahi = smem + SA_HI + (size_t)srow * PITCH * 2 + half * 64;
            char* alo = smem + SA_LO + (size_t)srow * PITCH * 2 + half * 64;
            #pragma unroll
            for (int v = 0; v < 8; v++) {
                float4 f = arow_ok ? src[v] : make_float4(0.f, 0.f, 0.f, 0.f);
                __nv_bfloat16 hx = __float2bfloat16(f.x), hy = __float2bfloat16(f.y);
                __nv_bfloat16 hz = __float2bfloat16(f.z), hw = __float2bfloat16(f.w);
                __nv_bfloat162 h01 = {hx, hy}, h23 = {hz, hw};
                __nv_bfloat162 l01 = {__float2bfloat16(f.x - __bfloat162float(hx)),
                                      __float2bfloat16(f.y - __bfloat162float(hy))};
                __nv_bfloat162 l23 = {__float2bfloat16(f.z - __bfloat162float(hz)),
                                      __float2bfloat16(f.w - __bfloat162float(hw))};
                *(uint32_t*)(ahi + v * 8)     = *(uint32_t*)&h01;
                *(uint32_t*)(ahi + v * 8 + 4) = *(uint32_t*)&h23;
                *(uint32_t*)(alo + v * 8)     = *(uint32_t*)&l01;
                *(uint32_t*)(alo + v * 8 + 4) = *(uint32_t*)&l23;
            }
        }
        // ---- stage B: copy W^T bf16 hi/lo (row srow = n, cols half*32..+32) ----
        {
            const uint4* shi = (const uint4*)(g_wt_hi + (size_t)srow * INDIM + k0 + half * 32);
            const uint4* slo = (const uint4*)(g_wt_lo + (size_t)srow * INDIM + k0 + half * 32);
            char* bhi = smem + SB_HI + (size_t)srow * PITCH * 2 + half * 64;
            char* blo = smem + SB_LO + (size_t)srow * PITCH * 2 + half * 64;
            #pragma unroll
            for (int v = 0; v < 4; v++) {
                *(uint4*)(bhi + v * 16) = shi[v];
                *(uint4*)(blo + v * 16) = slo[v];
            }
        }
        __syncthreads();

        // ---- 4 k16 steps x (2 mf x 8 nf x 3 products) HMMA ----
        #pragma unroll
        for (int ks = 0; ks < 4; ks++) {
            const int kk = ks * 16 + 2 * tq;     // bf16 col of this lane's pair
            uint32_t ahi[2][4], alo[2][4];
            #pragma unroll
            for (int mf = 0; mf < 2; mf++) {
                int r0 = wm * 32 + mf * 16 + groupID;
                const char* ph = smem + SA_HI;
                const char* pl = smem + SA_LO;
                ahi[mf][0] = *(const uint32_t*)(ph + ((size_t)r0 * PITCH + kk) * 2);
                ahi[mf][1] = *(const uint32_t*)(ph + ((size_t)(r0 + 8) * PITCH + kk) * 2);
                ahi[mf][2] = *(const uint32_t*)(ph + ((size_t)r0 * PITCH + kk + 8) * 2);
                ahi[mf][3] = *(const uint32_t*)(ph + ((size_t)(r0 + 8) * PITCH + kk + 8) * 2);
                alo[mf][0] = *(const uint32_t*)(pl + ((size_t)r0 * PITCH + kk) * 2);
                alo[mf][1] = *(const uint32_t*)(pl + ((size_t)(r0 + 8) * PITCH + kk) * 2);
                alo[mf][2] = *(const uint32_t*)(pl + ((size_t)r0 * PITCH + kk + 8) * 2);
                alo[mf][3] = *(const uint32_t*)(pl + ((size_t)(r0 + 8) * PITCH + kk + 8) * 2);
            }
            #pragma unroll
            for (int nf = 0; nf < 8; nf++) {
                int nr = wn * 64 + nf * 8 + groupID;
                uint32_t bh0 = *(const uint32_t*)(smem + SB_HI + ((size_t)nr * PITCH + kk) * 2);
                uint32_t bh1 = *(const uint32_t*)(smem + SB_HI + ((size_t)nr * PITCH + kk + 8) * 2);
                uint32_t bl0 = *(const uint32_t*)(smem + SB_LO + ((size_t)nr * PITCH + kk) * 2);
                uint32_t bl1 = *(const uint32_t*)(smem + SB_LO + ((size_t)nr * PITCH + kk + 8) * 2);
                #pragma unroll
                for (int mf = 0; mf < 2; mf++) {
                    mma16816(c[mf][nf], ahi[mf][0], ahi[mf][1], ahi[mf][2], ahi[mf][3], bh0, bh1);
                    mma16816(c[mf][nf], ahi[mf][0], ahi[mf][1], ahi[mf][2], ahi[mf][3], bl0, bl1);
                    mma16816(c[mf][nf], alo[mf][0], alo[mf][1], alo[mf][2], alo[mf][3], bh0, bh1);
                }
            }
        }
    }

    // ---- epilogue: c frags -> g_h ----
    #pragma unroll
    for (int mf = 0; mf < 2; mf++) {
        int r0 = m0 + wm * 32 + mf * 16 + groupID;
        #pragma unroll
        for (int nf = 0; nf < 8; nf++) {
            int n0 = wn * 64 + nf * 8 + 2 * tq;
            if (r0 < M)
                *(float2*)(g_h + (size_t)r0 * HID + n0) = make_float2(c[mf][nf][0], c[mf][nf][1]);
            if (r0 + 8 < M)
                *(float2*)(g_h + (size_t)(r0 + 8) * HID + n0) = make_float2(c[mf][nf][2], c[mf][nf][3]);
        }
    }
}

// ---------------- K2: in-degree on targets ----------------
__global__ void k_deg(const int* __restrict__ ei, int E) {
    int e = blockIdx.x * blockDim.x + threadIdx.x;
    if (e < E) atomicAdd(&g_degE[ei[E + e]], 1);
}

// ---------------- K3a/b/c: two-level scan -> rowptr, dinv ----------------
__global__ void k_scan1(int N) {
    __shared__ int sh[SCAN_BLK];
    int i = blockIdx.x * SCAN_BLK + threadIdx.x;
    int v = (i < N) ? g_degE[i] : 0;
    sh[threadIdx.x] = v;
    __syncthreads();
    #pragma unroll
    for (int off = 1; off < SCAN_BLK; off <<= 1) {
        int t = (threadIdx.x >= off) ? sh[threadIdx.x - off] : 0;
        __syncthreads();
        sh[threadIdx.x] += t;
        __syncthreads();
    }
    if (i < N) g_scan[i] = sh[threadIdx.x];
    if (threadIdx.x == SCAN_BLK - 1) g_bsum[blockIdx.x] = sh[SCAN_BLK - 1];
}
__global__ void k_scan2(int nblk) {
    __shared__ int sh[SCAN_BLK];
    int v = (threadIdx.x < nblk) ? g_bsum[threadIdx.x] : 0;
    sh[threadIdx.x] = v;
    __syncthreads();
    #pragma unroll
    for (int off = 1; off < SCAN_BLK; off <<= 1) {
        int t = (threadIdx.x >= off) ? sh[threadIdx.x - off] : 0;
        __syncthreads();
        sh[threadIdx.x] += t;
        __syncthreads();
    }
    g_bsum[threadIdx.x] = sh[threadIdx.x];
}
__global__ void k_scan3(int N) {
    int i = blockIdx.x * SCAN_BLK + threadIdx.x;
    if (i >= N) return;
    int base = (blockIdx.x > 0) ? g_bsum[blockIdx.x - 1] : 0;
    g_rowptr[i] = base + g_scan[i] - g_degE[i];
    g_dinv[i]   = rsqrtf((float)(g_degE[i] + 1));
}

// ---------------- K4: fill CSR source list ----------------
__global__ void k_fill(const int* __restrict__ ei, int E) {
    int e = blockIdx.x * blockDim.x + threadIdx.x;
    if (e >= E) return;
    int r = ei[e];
    int c = ei[E + e];
    int pos = atomicAdd(&g_cursor[c], 1);
    g_csr_src[g_rowptr[c] + pos] = r;
}

// ---------------- K5: gather-reduce, one warp per node ----------------
__global__ void k_gather(float* __restrict__ out, int N) {
    int g    = blockIdx.x * blockDim.x + threadIdx.x;
    int node = g >> 5;
    int lane = g & 31;
    if (node >= N) return;

    float di = g_dinv[node];
    float4 acc = ((const float4*)(g_h + (size_t)node * HID))[lane];
    float n2 = di * di;
    acc.x *= n2; acc.y *= n2; acc.z *= n2; acc.w *= n2;

    int s  = g_rowptr[node];
    int e2 = s + g_degE[node];
    for (int j = s; j < e2; j++) {
        int   r  = g_csr_src[j];
        float nr = di * g_dinv[r];
        float4 v = ((const float4*)(g_h + (size_t)r * HID))[lane];
        acc.x = fmaf(v.x, nr, acc.x);
        acc.y = fmaf(v.y, nr, acc.y);
        acc.z = fmaf(v.z, nr, acc.z);
        acc.w = fmaf(v.w, nr, acc.w);
    }
    ((float4*)(out + (size_t)node * HID))[lane] = acc;
}

// ---------------- K6: per-channel sum / sumsq ----------------
__global__ void k_colstat(const float* __restrict__ out, int N) {
    int ch  = threadIdx.x & 127;
    int sub = threadIdx.x >> 7;
    float s = 0.f, s2 = 0.f;
    for (int r = blockIdx.x * 4 + sub; r < N; r += gridDim.x * 4) {
        float v = out[(size_t)r * HID + ch];
        s += v; s2 += v * v;
    }
    __shared__ float sh[4][HID];
    __shared__ float sh2[4][HID];
    sh[sub][ch] = s; sh2[sub][ch] = s2;
    __syncthreads();
    if (sub == 0) {
        atomicAdd(&g_sum[ch],   sh[0][ch] + sh[1][ch] + sh[2][ch] + sh[3][ch]);
        atomicAdd(&g_sumsq[ch], sh2[0][ch] + sh2[1][ch] + sh2[2][ch] + sh2[3][ch]);
    }
}

// ---------------- K7: BN scale/shift (GCN bias b cancels inside BN) ----------------
__global__ void k_bnparam(int N, const float* __restrict__ gamma, const float* __restrict__ beta) {
    int c = threadIdx.x;
    float invN = 1.0f / (float)N;
    float mean = g_sum[c] * invN;
    float var  = g_sumsq[c] * invN - mean * mean;
    float sc   = gamma[c] * rsqrtf(var + BN_EPS);
    g_scale[c] = sc;
    g_shift[c] = beta[c] - mean * sc;
}

// ---------------- K8: y = relu(out*scale + shift), in place ----------------
__global__ void k_bnrelu(float* __restrict__ out, int total4) {
    int i = blockIdx.x * blockDim.x + threadIdx.x;
    if (i >= total4) return;
    float4 v  = ((const float4*)out)[i];
    int ch4   = i & 31;
    float4 sc = ((const float4*)g_scale)[ch4];
    float4 sh = ((const float4*)g_shift)[ch4];
    v.x = fmaxf(fmaf(v.x, sc.x, sh.x), 0.f);
    v.y = fmaxf(fmaf(v.y, sc.y, sh.y), 0.f);
    v.z = fmaxf(fmaf(v.z, sc.z, sh.z), 0.f);
    v.w = fmaxf(fmaf(v.w, sc.w, sh.w), 0.f);
    ((float4*)out)[i] = v;
}

// ---------------- launch ----------------
extern "C" void kernel_launch(void* const* d_in, const int* in_sizes, int n_in,
                              void* d_out, int out_size) {
    const float* x     = (const float*)d_in[0];
    const int*   ei    = (const int*)d_in[1];     // int32 (JAX x64 disabled)
    const float* W     = (const float*)d_in[2];
    // d_in[3] = b : cancels inside BatchNorm, unused
    const float* gamma = (const float*)d_in[4];
    const float* beta  = (const float*)d_in[5];
    float*       out   = (float*)d_out;

    const int N = in_sizes[0] / INDIM;     // 50000
    const int E = in_sizes[1] / 2;         // 600000
    const int nblk = (N + SCAN_BLK - 1) / SCAN_BLK;

    static int smem_set = 0;
    if (!smem_set) {
        cudaFuncSetAttribute(k_gemm_mma, cudaFuncAttributeMaxDynamicSharedMemorySize, SM_GEMM);
        smem_set = 1;
    }

    k_init<<<nblk, SCAN_BLK>>>(N);
    k_wsplit<<<HID, 256>>>(W);
    k_gemm_mma<<<(N + 127) / 128, 256, SM_GEMM>>>(x, N);
    k_deg<<<(E + 255) / 256, 256>>>(ei, E);
    k_scan1<<<nblk, SCAN_BLK>>>(N);
    k_scan2<<<1, SCAN_BLK>>>(nblk);
    k_scan3<<<nblk, SCAN_BLK>>>(N);
    k_fill<<<(E + 255) / 256, 256>>>(ei, E);
    k_gather<<<(N * 32 + 255) / 256, 256>>>(out, N);
    k_colstat<<<512, 512>>>(out, N);
    k_bnparam<<<1, HID>>>(N, gamma, beta);
    k_bnrelu<<<(N * 32 + 255) / 256, 256>>>(out, N * 32);
}

// round 6
// speedup vs baseline: 1.4874x; 1.0163x over previous
#include <cuda_runtime.h>
#include <cuda_bf16.h>
#include <cstdint>

#define NMAX 50000
#define EMAX 600000
#define HID 128
#define INDIM 256
#define BN_EPS 1e-5f
#define SCAN_BLK 256

// ---------------- scratch (no allocations allowed) ----------------
__device__ float g_h[(size_t)NMAX * HID];         // x @ W
__device__ __nv_bfloat16 g_wt_hi[HID * INDIM];    // W^T split hi: [n][k]
__device__ __nv_bfloat16 g_wt_lo[HID * INDIM];    // W^T split lo: [n][k]
__device__ int   g_degE[NMAX];
__device__ int   g_scan[NMAX];
__device__ int   g_rowptr[NMAX];
__device__ int   g_cursor[NMAX];
__device__ int   g_bsum[SCAN_BLK];
__device__ int   g_csr_src[EMAX];
__device__ float g_dinv[NMAX];
__device__ float g_sum[HID];
__device__ float g_sumsq[HID];
__device__ float g_scale[HID];
__device__ float g_shift[HID];

// ---------------- K0: zero all per-run state ----------------
__global__ void k_init(int N) {
    int i = blockIdx.x * blockDim.x + threadIdx.x;
    if (i < N) { g_degE[i] = 0; g_cursor[i] = 0; }
    if (i < HID) { g_sum[i] = 0.0f; g_sumsq[i] = 0.0f; }
    if (i < SCAN_BLK) g_bsum[i] = 0;
}

// ---------------- Kw: transpose + bf16-split W -> g_wt_hi/lo [n][k] ----------------
__global__ void k_wsplit(const float* __restrict__ W) {
    int n = blockIdx.x;
    for (int k = threadIdx.x; k < INDIM; k += blockDim.x) {
        float f = W[(size_t)k * HID + n];
        __nv_bfloat16 h = __float2bfloat16(f);
        float r = f - __bfloat162float(h);
        g_wt_hi[n * INDIM + k] = h;
        g_wt_lo[n * INDIM + k] = __float2bfloat16(r);
    }
}

// ================= K1: HMMA GEMM  h = x @ W  via bf16-split =================
#define PITCH 72
#define PLANE (128 * PITCH * 2)          // bytes per plane = 18432
#define SA_HI 0
#define SA_LO (PLANE)
#define SB_HI (2 * PLANE)
#define SB_LO (3 * PLANE)
#define SM_GEMM (4 * PLANE)              // 73728 B

__device__ __forceinline__ void mma16816(float c[4], uint32_t a0, uint32_t a1,
                                         uint32_t a2, uint32_t a3,
                                         uint32_t b0, uint32_t b1) {
    asm volatile("mma.sync.aligned.m16n8k16.row.col.f32.bf16.bf16.f32 "
                 "{%0,%1,%2,%3},{%4,%5,%6,%7},{%8,%9},{%0,%1,%2,%3};"
                 : "+f"(c[0]), "+f"(c[1]), "+f"(c[2]), "+f"(c[3])
                 : "r"(a0), "r"(a1), "r"(a2), "r"(a3), "r"(b0), "r"(b1));
}

__global__ __launch_bounds__(256, 1)
void k_gemm_mma(const float* __restrict__ x, int M) {
    extern __shared__ char smem[];
    const int tid  = threadIdx.x;
    const int wid  = tid >> 5;
    const int lane = tid & 31;
    const int m0   = blockIdx.x * 128;

    const int wm = wid & 3;         // 4 M-subtiles of 32
    const int wn = wid >> 2;        // 2 N-subtiles of 64

    float c[2][8][4];
    #pragma unroll
    for (int mf = 0; mf < 2; mf++)
        #pragma unroll
        for (int nf = 0; nf < 8; nf++)
            #pragma unroll
            for (int q = 0; q < 4; q++) c[mf][nf][q] = 0.0f;

    const int srow = tid >> 1;          // 0..127 (loader row)
    const int half = tid & 1;           // 32-col half of the 64-wide chunk
    const bool arow_ok = (m0 + srow) < M;

    const int groupID = lane >> 2;
    const int tq      = lane & 3;

    const float4* xsrc = (const float4*)(x + (size_t)(m0 + srow) * INDIM + half * 32);
    const uint4*  whsrc = (const uint4*)(g_wt_hi + (size_t)srow * INDIM + half * 32);
    const uint4*  wlsrc = (const uint4*)(g_wt_lo + (size_t)srow * INDIM + half * 32);

    float4 fx[8];
    uint4  bh[4], bl[4];

    // prologue: load chunk 0
    #pragma unroll
    for (int v = 0; v < 8; v++)
        fx[v] = arow_ok ? xsrc[v] : make_float4(0.f, 0.f, 0.f, 0.f);
    #pragma unroll
    for (int v = 0; v < 4; v++) { bh[v] = whsrc[v]; bl[v] = wlsrc[v]; }

    #pragma unroll 1
    for (int ch = 0; ch < INDIM / 64; ch++) {
        // ---- stage registers -> smem (convert A to bf16 hi/lo) ----
        {
            char* ahi = smem + SA_HI + (size_t)srow * PITCH * 2 + half * 64;
            char* alo = smem + SA_LO + (size_t)srow * PITCH * 2 + half * 64;
            #pragma unroll
            for (int v = 0; v < 8; v++) {
                float4 f = fx[v];
                __nv_bfloat16 hx = __float2bfloat16(f.x), hy = __float2bfloat16(f.y);
                __nv_bfloat16 hz = __float2bfloat16(f.z), hw = __float2bfloat16(f.w);
                __nv_bfloat162 h01 = {hx, hy}, h23 = {hz, hw};
                __nv_bfloat162 l01 = {__float2bfloat16(f.x - __bfloat162float(hx)),
                                      __float2bfloat16(f.y - __bfloat162float(hy))};
                __nv_bfloat162 l23 = {__float2bfloat16(f.z - __bfloat162float(hz)),
                                      __float2bfloat16(f.w - __bfloat162float(hw))};
                *(uint32_t*)(ahi + v * 8)     = *(uint32_t*)&h01;
                *(uint32_t*)(ahi + v * 8 + 4) = *(uint32_t*)&h23;
                *(uint32_t*)(alo + v * 8)     = *(uint32_t*)&l01;
                *(uint32_t*)(alo + v * 8 + 4) = *(uint32_t*)&l23;
            }
            char* bhi = smem + SB_HI + (size_t)srow * PITCH * 2 + half * 64;
            char* blo = smem + SB_LO + (size_t)srow * PITCH * 2 + half * 64;
            #pragma unroll
            for (int v = 0; v < 4; v++) {
                *(uint4*)(bhi + v * 16) = bh[v];
                *(uint4*)(blo + v * 16) = bl[v];
            }
        }
        __syncthreads();

        // ---- prefetch next chunk while MMAs run ----
        if (ch < INDIM / 64 - 1) {
            const int koff = (ch + 1) * 8;       // float4 offset (64 floats / 8 per f4... 16 f4 per 64 cols? 64 floats = 16 float4; but per-thread half covers 32 floats = 8 float4)
            #pragma unroll
            for (int v = 0; v < 8; v++)
                fx[v] = arow_ok ? xsrc[(ch + 1) * 16 + v] : make_float4(0.f, 0.f, 0.f, 0.f);
            #pragma unroll
            for (int v = 0; v < 4; v++) {
                bh[v] = whsrc[(ch + 1) * 8 + v];
                bl[v] = wlsrc[(ch + 1) * 8 + v];
            }
            (void)koff;
        }

        // ---- 4 k16 steps x (2 mf x 8 nf x 3 products) HMMA ----
        #pragma unroll
        for (int ks = 0; ks < 4; ks++) {
            const int kk = ks * 16 + 2 * tq;
            uint32_t ahi[2][4], alo[2][4];
            #pragma unroll
            for (int mf = 0; mf < 2; mf++) {
                int r0 = wm * 32 + mf * 16 + groupID;
                const char* ph = smem + SA_HI;
                const char* pl = smem + SA_LO;
                ahi[mf][0] = *(const uint32_t*)(ph + ((size_t)r0 * PITCH + kk) * 2);
                ahi[mf][1] = *(const uint32_t*)(ph + ((size_t)(r0 + 8) * PITCH + kk) * 2);
                ahi[mf][2] = *(const uint32_t*)(ph + ((size_t)r0 * PITCH + kk + 8) * 2);
                ahi[mf][3] = *(const uint32_t*)(ph + ((size_t)(r0 + 8) * PITCH + kk + 8) * 2);
                alo[mf][0] = *(const uint32_t*)(pl + ((size_t)r0 * PITCH + kk) * 2);
                alo[mf][1] = *(const uint32_t*)(pl + ((size_t)(r0 + 8) * PITCH + kk) * 2);
                alo[mf][2] = *(const uint32_t*)(pl + ((size_t)r0 * PITCH + kk + 8) * 2);
                alo[mf][3] = *(const uint32_t*)(pl + ((size_t)(r0 + 8) * PITCH + kk + 8) * 2);
            }
            #pragma unroll
            for (int nf = 0; nf < 8; nf++) {
                int nr = wn * 64 + nf * 8 + groupID;
                uint32_t bh0 = *(const uint32_t*)(smem + SB_HI + ((size_t)nr * PITCH + kk) * 2);
                uint32_t bh1 = *(const uint32_t*)(smem + SB_HI + ((size_t)nr * PITCH + kk + 8) * 2);
                uint32_t bl0 = *(const uint32_t*)(smem + SB_LO + ((size_t)nr * PITCH + kk) * 2);
                uint32_t bl1 = *(const uint32_t*)(smem + SB_LO + ((size_t)nr * PITCH + kk + 8) * 2);
                #pragma unroll
                for (int mf = 0; mf < 2; mf++) {
                    mma16816(c[mf][nf], ahi[mf][0], ahi[mf][1], ahi[mf][2], ahi[mf][3], bh0, bh1);
                    mma16816(c[mf][nf], ahi[mf][0], ahi[mf][1], ahi[mf][2], ahi[mf][3], bl0, bl1);
                    mma16816(c[mf][nf], alo[mf][0], alo[mf][1], alo[mf][2], alo[mf][3], bh0, bh1);
                }
            }
        }
        if (ch < INDIM / 64 - 1) __syncthreads();
    }

    // ---- epilogue: c frags -> g_h ----
    #pragma unroll
    for (int mf = 0; mf < 2; mf++) {
        int r0 = m0 + wm * 32 + mf * 16 + groupID;
        #pragma unroll
        for (int nf = 0; nf < 8; nf++) {
            int n0 = wn * 64 + nf * 8 + 2 * tq;
            if (r0 < M)
                *(float2*)(g_h + (size_t)r0 * HID + n0) = make_float2(c[mf][nf][0], c[mf][nf][1]);
            if (r0 + 8 < M)
                *(float2*)(g_h + (size_t)(r0 + 8) * HID + n0) = make_float2(c[mf][nf][2], c[mf][nf][3]);
        }
    }
}

// ---------------- K2: in-degree on targets (4 edges/thread, int4) ----------------
__global__ void k_deg(const int* __restrict__ ei, int E) {
    int t = blockIdx.x * blockDim.x + threadIdx.x;
    int e4 = t * 4;
    if (e4 + 3 < E) {
        int4 cc = *(const int4*)(ei + E + e4);
        atomicAdd(&g_degE[cc.x], 1);
        atomicAdd(&g_degE[cc.y], 1);
        atomicAdd(&g_degE[cc.z], 1);
        atomicAdd(&g_degE[cc.w], 1);
    } else {
        for (int e = e4; e < E; e++) atomicAdd(&g_degE[ei[E + e]], 1);
    }
}

// ---------------- K3a/b/c: two-level scan -> rowptr, dinv ----------------
__global__ void k_scan1(int N) {
    __shared__ int sh[SCAN_BLK];
    int i = blockIdx.x * SCAN_BLK + threadIdx.x;
    int v = (i < N) ? g_degE[i] : 0;
    sh[threadIdx.x] = v;
    __syncthreads();
    #pragma unroll
    for (int off = 1; off < SCAN_BLK; off <<= 1) {
        int t = (threadIdx.x >= off) ? sh[threadIdx.x - off] : 0;
        __syncthreads();
        sh[threadIdx.x] += t;
        __syncthreads();
    }
    if (i < N) g_scan[i] = sh[threadIdx.x];
    if (threadIdx.x == SCAN_BLK - 1) g_bsum[blockIdx.x] = sh[SCAN_BLK - 1];
}
__global__ void k_scan2(int nblk) {
    __shared__ int sh[SCAN_BLK];
    int v = (threadIdx.x < nblk) ? g_bsum[threadIdx.x] : 0;
    sh[threadIdx.x] = v;
    __syncthreads();
    #pragma unroll
    for (int off = 1; off < SCAN_BLK; off <<= 1) {
        int t = (threadIdx.x >= off) ? sh[threadIdx.x - off] : 0;
        __syncthreads();
        sh[threadIdx.x] += t;
        __syncthreads();
    }
    g_bsum[threadIdx.x] = sh[threadIdx.x];
}
__global__ void k_scan3(int N) {
    int i = blockIdx.x * SCAN_BLK + threadIdx.x;
    if (i >= N) return;
    int base = (blockIdx.x > 0) ? g_bsum[blockIdx.x - 1] : 0;
    g_rowptr[i] = base + g_scan[i] - g_degE[i];
    g_dinv[i]   = rsqrtf((float)(g_degE[i] + 1));
}

// ---------------- K4: fill CSR source list (4 edges/thread) ----------------
__global__ void k_fill(const int* __restrict__ ei, int E) {
    int t = blockIdx.x * blockDim.x + threadIdx.x;
    int e4 = t * 4;
    if (e4 + 3 < E) {
        int4 rr = *(const int4*)(ei + e4);
        int4 cc = *(const int4*)(ei + E + e4);
        int p;
        p = atomicAdd(&g_cursor[cc.x], 1); g_csr_src[g_rowptr[cc.x] + p] = rr.x;
        p = atomicAdd(&g_cursor[cc.y], 1); g_csr_src[g_rowptr[cc.y] + p] = rr.y;
        p = atomicAdd(&g_cursor[cc.z], 1); g_csr_src[g_rowptr[cc.z] + p] = rr.z;
        p = atomicAdd(&g_cursor[cc.w], 1); g_csr_src[g_rowptr[cc.w] + p] = rr.w;
    } else {
        for (int e = e4; e < E; e++) {
            int r = ei[e], c = ei[E + e];
            int p = atomicAdd(&g_cursor[c], 1);
            g_csr_src[g_rowptr[c] + p] = r;
        }
    }
}

// ---------------- K5: gather-reduce + fused BN stats ----------------
// 8 nodes per 256-thread block (one warp each); block-level channel reduction.
__global__ void k_gather(float* __restrict__ out, int N) {
    __shared__ float sh[8][HID];
    __shared__ float sh2[8][HID];
    const int wid  = threadIdx.x >> 5;
    const int lane = threadIdx.x & 31;
    const int node = blockIdx.x * 8 + wid;

    float4 acc = make_float4(0.f, 0.f, 0.f, 0.f);
    if (node < N) {
        float di = g_dinv[node];
        acc = ((const float4*)(g_h + (size_t)node * HID))[lane];
        float n2 = di * di;
        acc.x *= n2; acc.y *= n2; acc.z *= n2; acc.w *= n2;

        int s  = g_rowptr[node];
        int e2 = s + g_degE[node];
        for (int j = s; j < e2; j++) {
            int   r  = g_csr_src[j];
            float nr = di * g_dinv[r];
            float4 v = ((const float4*)(g_h + (size_t)r * HID))[lane];
            acc.x = fmaf(v.x, nr, acc.x);
            acc.y = fmaf(v.y, nr, acc.y);
            acc.z = fmaf(v.z, nr, acc.z);
            acc.w = fmaf(v.w, nr, acc.w);
        }
        ((float4*)(out + (size_t)node * HID))[lane] = acc;
    }

    *(float4*)&sh[wid][lane * 4]  = acc;
    *(float4*)&sh2[wid][lane * 4] = make_float4(acc.x * acc.x, acc.y * acc.y,
                                                acc.z * acc.z, acc.w * acc.w);
    __syncthreads();
    if (threadIdx.x < HID) {
        float s = 0.f, s2 = 0.f;
        #pragma unroll
        for (int w = 0; w < 8; w++) { s += sh[w][threadIdx.x]; s2 += sh2[w][threadIdx.x]; }
        atomicAdd(&g_sum[threadIdx.x],   s);
        atomicAdd(&g_sumsq[threadIdx.x], s2);
    }
}

// ---------------- K7: BN scale/shift (GCN bias b cancels inside BN) ----------------
__global__ void k_bnparam(int N, const float* __restrict__ gamma, const float* __restrict__ beta) {
    int c = threadIdx.x;
    float invN = 1.0f / (float)N;
    float mean = g_sum[c] * invN;
    float var  = g_sumsq[c] * invN - mean * mean;
    float sc   = gamma[c] * rsqrtf(var + BN_EPS);
    g_scale[c] = sc;
    g_shift[c] = beta[c] - mean * sc;
}

// ---------------- K8: y = relu(out*scale + shift), in place ----------------
__global__ void k_bnrelu(float* __restrict__ out, int total4) {
    int i = blockIdx.x * blockDim.x + threadIdx.x;
    if (i >= total4) return;
    float4 v  = ((const float4*)out)[i];
    int ch4   = i & 31;
    float4 sc = ((const float4*)g_scale)[ch4];
    float4 sh = ((const float4*)g_shift)[ch4];
    v.x = fmaxf(fmaf(v.x, sc.x, sh.x), 0.f);
    v.y = fmaxf(fmaf(v.y, sc.y, sh.y), 0.f);
    v.z = fmaxf(fmaf(v.z, sc.z, sh.z), 0.f);
    v.w = fmaxf(fmaf(v.w, sc.w, sh.w), 0.f);
    ((float4*)out)[i] = v;
}

// ---------------- launch ----------------
extern "C" void kernel_launch(void* const* d_in, const int* in_sizes, int n_in,
                              void* d_out, int out_size) {
    const float* x     = (const float*)d_in[0];
    const int*   ei    = (const int*)d_in[1];     // int32 (JAX x64 disabled)
    const float* W     = (const float*)d_in[2];
    // d_in[3] = b : cancels inside BatchNorm, unused
    const float* gamma = (const float*)d_in[4];
    const float* beta  = (const float*)d_in[5];
    float*       out   = (float*)d_out;

    const int N = in_sizes[0] / INDIM;     // 50000
    const int E = in_sizes[1] / 2;         // 600000
    const int nblk = (N + SCAN_BLK - 1) / SCAN_BLK;

    static int smem_set = 0;
    if (!smem_set) {
        cudaFuncSetAttribute(k_gemm_mma, cudaFuncAttributeMaxDynamicSharedMemorySize, SM_GEMM);
        smem_set = 1;
    }

    k_init<<<nblk, SCAN_BLK>>>(N);
    k_wsplit<<<HID, 256>>>(W);
    k_gemm_mma<<<(N + 127) / 128, 256, SM_GEMM>>>(x, N);
    k_deg<<<((E + 3) / 4 + 255) / 256, 256>>>(ei, E);
    k_scan1<<<nblk, SCAN_BLK>>>(N);
    k_scan2<<<1, SCAN_BLK>>>(nblk);
    k_scan3<<<nblk, SCAN_BLK>>>(N);
    k_fill<<<((E + 3) / 4 + 255) / 256, 256>>>(ei, E);
    k_gather<<<(N + 7) / 8, 256>>>(out, N);
    k_bnparam<<<1, HID>>>(N, gamma, beta);
    k_bnrelu<<<(N * 32 + 255) / 256, 256>>>(out, N * 32);
}

// round 7
// speedup vs baseline: 1.7104x; 1.1499x over previous
#include <cuda_runtime.h>
#include <cuda_bf16.h>
#include <cstdint>

#define NMAX 50000
#define EMAX 600000
#define HID 128
#define INDIM 256
#define BN_EPS 1e-5f
#define SCAN_BLK 256

// ---------------- scratch (no allocations allowed) ----------------
__device__ float g_h[(size_t)NMAX * HID];         // x @ W
__device__ __nv_bfloat16 g_wt_hi[HID * INDIM];    // W^T split hi: [n][k]
__device__ __nv_bfloat16 g_wt_lo[HID * INDIM];    // W^T split lo: [n][k]
__device__ int   g_degE[NMAX];
__device__ int   g_scan[NMAX];
__device__ int   g_rowptr[NMAX];
__device__ int   g_cursor[NMAX];
__device__ int   g_bsum[SCAN_BLK];
__device__ int   g_csr_src[EMAX];
__device__ float g_dinv[NMAX];
__device__ float g_sum[HID];
__device__ float g_sumsq[HID];
__device__ float g_scale[HID];
__device__ float g_shift[HID];

// ---------------- K0: zero all per-run state ----------------
__global__ void k_init(int N) {
    int i = blockIdx.x * blockDim.x + threadIdx.x;
    if (i < N) { g_degE[i] = 0; g_cursor[i] = 0; }
    if (i < HID) { g_sum[i] = 0.0f; g_sumsq[i] = 0.0f; }
    if (i < SCAN_BLK) g_bsum[i] = 0;
}

// ---------------- Kw: transpose + bf16-split W -> g_wt_hi/lo [n][k] ----------------
__global__ void k_wsplit(const float* __restrict__ W) {
    int n = blockIdx.x;
    for (int k = threadIdx.x; k < INDIM; k += blockDim.x) {
        float f = W[(size_t)k * HID + n];
        __nv_bfloat16 h = __float2bfloat16(f);
        float r = f - __bfloat162float(h);
        g_wt_hi[n * INDIM + k] = h;
        g_wt_lo[n * INDIM + k] = __float2bfloat16(r);
    }
}

// ================= K1: HMMA GEMM  h = x @ W  via bf16-split =================
#define PITCH 72
#define PLANE (128 * PITCH * 2)          // bytes per plane = 18432
#define SA_HI 0
#define SA_LO (PLANE)
#define SB_HI (2 * PLANE)
#define SB_LO (3 * PLANE)
#define SM_GEMM (4 * PLANE)              // 73728 B

__device__ __forceinline__ void mma16816(float c[4], uint32_t a0, uint32_t a1,
                                         uint32_t a2, uint32_t a3,
                                         uint32_t b0, uint32_t b1) {
    asm volatile("mma.sync.aligned.m16n8k16.row.col.f32.bf16.bf16.f32 "
                 "{%0,%1,%2,%3},{%4,%5,%6,%7},{%8,%9},{%0,%1,%2,%3};"
                 : "+f"(c[0]), "+f"(c[1]), "+f"(c[2]), "+f"(c[3])
                 : "r"(a0), "r"(a1), "r"(a2), "r"(a3), "r"(b0), "r"(b1));
}

__global__ __launch_bounds__(256, 1)
void k_gemm_mma(const float* __restrict__ x, int M) {
    extern __shared__ char smem[];
    const int tid  = threadIdx.x;
    const int wid  = tid >> 5;
    const int lane = tid & 31;
    const int m0   = blockIdx.x * 128;

    const int wm = wid & 3;
    const int wn = wid >> 2;

    float c[2][8][4];
    #pragma unroll
    for (int mf = 0; mf < 2; mf++)
        #pragma unroll
        for (int nf = 0; nf < 8; nf++)
            #pragma unroll
            for (int q = 0; q < 4; q++) c[mf][nf][q] = 0.0f;

    const int srow = tid >> 1;
    const int half = tid & 1;
    const bool arow_ok = (m0 + srow) < M;

    const int groupID = lane >> 2;
    const int tq      = lane & 3;

    const float4* xsrc  = (const float4*)(x + (size_t)(m0 + srow) * INDIM + half * 32);
    const uint4*  whsrc = (const uint4*)(g_wt_hi + (size_t)srow * INDIM + half * 32);
    const uint4*  wlsrc = (const uint4*)(g_wt_lo + (size_t)srow * INDIM + half * 32);

    float4 fx[8];
    uint4  bh[4], bl[4];

    #pragma unroll
    for (int v = 0; v < 8; v++)
        fx[v] = arow_ok ? xsrc[v] : make_float4(0.f, 0.f, 0.f, 0.f);
    #pragma unroll
    for (int v = 0; v < 4; v++) { bh[v] = whsrc[v]; bl[v] = wlsrc[v]; }

    #pragma unroll 1
    for (int ch = 0; ch < INDIM / 64; ch++) {
        {
            char* ahi = smem + SA_HI + (size_t)srow * PITCH * 2 + half * 64;
            char* alo = smem + SA_LO + (size_t)srow * PITCH * 2 + half * 64;
            #pragma unroll
            for (int v = 0; v < 8; v++) {
                float4 f = fx[v];
                __nv_bfloat16 hx = __float2bfloat16(f.x), hy = __float2bfloat16(f.y);
                __nv_bfloat16 hz = __float2bfloat16(f.z), hw = __float2bfloat16(f.w);
                __nv_bfloat162 h01 = {hx, hy}, h23 = {hz, hw};
                __nv_bfloat162 l01 = {__float2bfloat16(f.x - __bfloat162float(hx)),
                                      __float2bfloat16(f.y - __bfloat162float(hy))};
                __nv_bfloat162 l23 = {__float2bfloat16(f.z - __bfloat162float(hz)),
                                      __float2bfloat16(f.w - __bfloat162float(hw))};
                *(uint32_t*)(ahi + v * 8)     = *(uint32_t*)&h01;
                *(uint32_t*)(ahi + v * 8 + 4) = *(uint32_t*)&h23;
                *(uint32_t*)(alo + v * 8)     = *(uint32_t*)&l01;
                *(uint32_t*)(alo + v * 8 + 4) = *(uint32_t*)&l23;
            }
            char* bhi = smem + SB_HI + (size_t)srow * PITCH * 2 + half * 64;
            char* blo = smem + SB_LO + (size_t)srow * PITCH * 2 + half * 64;
            #pragma unroll
            for (int v = 0; v < 4; v++) {
                *(uint4*)(bhi + v * 16) = bh[v];
                *(uint4*)(blo + v * 16) = bl[v];
            }
        }
        __syncthreads();

        if (ch < INDIM / 64 - 1) {
            #pragma unroll
            for (int v = 0; v < 8; v++)
                fx[v] = arow_ok ? xsrc[(ch + 1) * 16 + v] : make_float4(0.f, 0.f, 0.f, 0.f);
            #pragma unroll
            for (int v = 0; v < 4; v++) {
                bh[v] = whsrc[(ch + 1) * 8 + v];
                bl[v] = wlsrc[(ch + 1) * 8 + v];
            }
        }

        #pragma unroll
        for (int ks = 0; ks < 4; ks++) {
            const int kk = ks * 16 + 2 * tq;
            uint32_t ahi[2][4], alo[2][4];
            #pragma unroll
            for (int mf = 0; mf < 2; mf++) {
                int r0 = wm * 32 + mf * 16 + groupID;
                const char* ph = smem + SA_HI;
                const char* pl = smem + SA_LO;
                ahi[mf][0] = *(const uint32_t*)(ph + ((size_t)r0 * PITCH + kk) * 2);
                ahi[mf][1] = *(const uint32_t*)(ph + ((size_t)(r0 + 8) * PITCH + kk) * 2);
                ahi[mf][2] = *(const uint32_t*)(ph + ((size_t)r0 * PITCH + kk + 8) * 2);
                ahi[mf][3] = *(const uint32_t*)(ph + ((size_t)(r0 + 8) * PITCH + kk + 8) * 2);
                alo[mf][0] = *(const uint32_t*)(pl + ((size_t)r0 * PITCH + kk) * 2);
                alo[mf][1] = *(const uint32_t*)(pl + ((size_t)(r0 + 8) * PITCH + kk) * 2);
                alo[mf][2] = *(const uint32_t*)(pl + ((size_t)r0 * PITCH + kk + 8) * 2);
                alo[mf][3] = *(const uint32_t*)(pl + ((size_t)(r0 + 8) * PITCH + kk + 8) * 2);
            }
            #pragma unroll
            for (int nf = 0; nf < 8; nf++) {
                int nr = wn * 64 + nf * 8 + groupID;
                uint32_t bh0 = *(const uint32_t*)(smem + SB_HI + ((size_t)nr * PITCH + kk) * 2);
                uint32_t bh1 = *(const uint32_t*)(smem + SB_HI + ((size_t)nr * PITCH + kk + 8) * 2);
                uint32_t bl0 = *(const uint32_t*)(smem + SB_LO + ((size_t)nr * PITCH + kk) * 2);
                uint32_t bl1 = *(const uint32_t*)(smem + SB_LO + ((size_t)nr * PITCH + kk + 8) * 2);
                #pragma unroll
                for (int mf = 0; mf < 2; mf++) {
                    mma16816(c[mf][nf], ahi[mf][0], ahi[mf][1], ahi[mf][2], ahi[mf][3], bh0, bh1);
                    mma16816(c[mf][nf], ahi[mf][0], ahi[mf][1], ahi[mf][2], ahi[mf][3], bl0, bl1);
                    mma16816(c[mf][nf], alo[mf][0], alo[mf][1], alo[mf][2], alo[mf][3], bh0, bh1);
                }
            }
        }
        if (ch < INDIM / 64 - 1) __syncthreads();
    }

    #pragma unroll
    for (int mf = 0; mf < 2; mf++) {
        int r0 = m0 + wm * 32 + mf * 16 + groupID;
        #pragma unroll
        for (int nf = 0; nf < 8; nf++) {
            int n0 = wn * 64 + nf * 8 + 2 * tq;
            if (r0 < M)
                *(float2*)(g_h + (size_t)r0 * HID + n0) = make_float2(c[mf][nf][0], c[mf][nf][1]);
            if (r0 + 8 < M)
                *(float2*)(g_h + (size_t)(r0 + 8) * HID + n0) = make_float2(c[mf][nf][2], c[mf][nf][3]);
        }
    }
}

// ---------------- K2: in-degree on targets (4 edges/thread, int4) ----------------
__global__ void k_deg(const int* __restrict__ ei, int E) {
    int t = blockIdx.x * blockDim.x + threadIdx.x;
    int e4 = t * 4;
    if (e4 + 3 < E) {
        int4 cc = *(const int4*)(ei + E + e4);
        atomicAdd(&g_degE[cc.x], 1);
        atomicAdd(&g_degE[cc.y], 1);
        atomicAdd(&g_degE[cc.z], 1);
        atomicAdd(&g_degE[cc.w], 1);
    } else {
        for (int e = e4; e < E; e++) atomicAdd(&g_degE[ei[E + e]], 1);
    }
}

// ---------------- K3a/b/c: two-level scan -> rowptr, dinv ----------------
__global__ void k_scan1(int N) {
    __shared__ int sh[SCAN_BLK];
    int i = blockIdx.x * SCAN_BLK + threadIdx.x;
    int v = (i < N) ? g_degE[i] : 0;
    sh[threadIdx.x] = v;
    __syncthreads();
    #pragma unroll
    for (int off = 1; off < SCAN_BLK; off <<= 1) {
        int t = (threadIdx.x >= off) ? sh[threadIdx.x - off] : 0;
        __syncthreads();
        sh[threadIdx.x] += t;
        __syncthreads();
    }
    if (i < N) g_scan[i] = sh[threadIdx.x];
    if (threadIdx.x == SCAN_BLK - 1) g_bsum[blockIdx.x] = sh[SCAN_BLK - 1];
}
__global__ void k_scan2(int nblk) {
    __shared__ int sh[SCAN_BLK];
    int v = (threadIdx.x < nblk) ? g_bsum[threadIdx.x] : 0;
    sh[threadIdx.x] = v;
    __syncthreads();
    #pragma unroll
    for (int off = 1; off < SCAN_BLK; off <<= 1) {
        int t = (threadIdx.x >= off) ? sh[threadIdx.x - off] : 0;
        __syncthreads();
        sh[threadIdx.x] += t;
        __syncthreads();
    }
    g_bsum[threadIdx.x] = sh[threadIdx.x];
}
__global__ void k_scan3(int N) {
    int i = blockIdx.x * SCAN_BLK + threadIdx.x;
    if (i >= N) return;
    int base = (blockIdx.x > 0) ? g_bsum[blockIdx.x - 1] : 0;
    g_rowptr[i] = base + g_scan[i] - g_degE[i];
    g_dinv[i]   = rsqrtf((float)(g_degE[i] + 1));
}

// ---------------- K4: fill CSR source list (4 edges/thread) ----------------
__global__ void k_fill(const int* __restrict__ ei, int E) {
    int t = blockIdx.x * blockDim.x + threadIdx.x;
    int e4 = t * 4;
    if (e4 + 3 < E) {
        int4 rr = *(const int4*)(ei + e4);
        int4 cc = *(const int4*)(ei + E + e4);
        int p;
        p = atomicAdd(&g_cursor[cc.x], 1); g_csr_src[g_rowptr[cc.x] + p] = rr.x;
        p = atomicAdd(&g_cursor[cc.y], 1); g_csr_src[g_rowptr[cc.y] + p] = rr.y;
        p = atomicAdd(&g_cursor[cc.z], 1); g_csr_src[g_rowptr[cc.z] + p] = rr.z;
        p = atomicAdd(&g_cursor[cc.w], 1); g_csr_src[g_rowptr[cc.w] + p] = rr.w;
    } else {
        for (int e = e4; e < E; e++) {
            int r = ei[e], c = ei[E + e];
            int p = atomicAdd(&g_cursor[c], 1);
            g_csr_src[g_rowptr[c] + p] = r;
        }
    }
}

// ---------------- K5: gather-reduce + fused BN stats ----------------
__global__ void k_gather(float* __restrict__ out, int N) {
    __shared__ float sh[8][HID];
    __shared__ float sh2[8][HID];
    const int wid  = threadIdx.x >> 5;
    const int lane = threadIdx.x & 31;
    const int node = blockIdx.x * 8 + wid;

    float4 acc = make_float4(0.f, 0.f, 0.f, 0.f);
    if (node < N) {
        float di = g_dinv[node];
        acc = ((const float4*)(g_h + (size_t)node * HID))[lane];
        float n2 = di * di;
        acc.x *= n2; acc.y *= n2; acc.z *= n2; acc.w *= n2;

        int s  = g_rowptr[node];
        int e2 = s + g_degE[node];
        for (int j = s; j < e2; j++) {
            int   r  = g_csr_src[j];
            float nr = di * g_dinv[r];
            float4 v = ((const float4*)(g_h + (size_t)r * HID))[lane];
            acc.x = fmaf(v.x, nr, acc.x);
            acc.y = fmaf(v.y, nr, acc.y);
            acc.z = fmaf(v.z, nr, acc.z);
            acc.w = fmaf(v.w, nr, acc.w);
        }
        ((float4*)(out + (size_t)node * HID))[lane] = acc;
    }

    *(float4*)&sh[wid][lane * 4]  = acc;
    *(float4*)&sh2[wid][lane * 4] = make_float4(acc.x * acc.x, acc.y * acc.y,
                                                acc.z * acc.z, acc.w * acc.w);
    __syncthreads();
    if (threadIdx.x < HID) {
        float s = 0.f, s2 = 0.f;
        #pragma unroll
        for (int w = 0; w < 8; w++) { s += sh[w][threadIdx.x]; s2 += sh2[w][threadIdx.x]; }
        atomicAdd(&g_sum[threadIdx.x],   s);
        atomicAdd(&g_sumsq[threadIdx.x], s2);
    }
}

// ---------------- K7: BN scale/shift ----------------
__global__ void k_bnparam(int N, const float* __restrict__ gamma, const float* __restrict__ beta) {
    int c = threadIdx.x;
    float invN = 1.0f / (float)N;
    float mean = g_sum[c] * invN;
    float var  = g_sumsq[c] * invN - mean * mean;
    float sc   = gamma[c] * rsqrtf(var + BN_EPS);
    g_scale[c] = sc;
    g_shift[c] = beta[c] - mean * sc;
}

// ---------------- K8: y = relu(out*scale + shift), in place ----------------
__global__ void k_bnrelu(float* __restrict__ out, int total4) {
    int i = blockIdx.x * blockDim.x + threadIdx.x;
    if (i >= total4) return;
    float4 v  = ((const float4*)out)[i];
    int ch4   = i & 31;
    float4 sc = ((const float4*)g_scale)[ch4];
    float4 sh = ((const float4*)g_shift)[ch4];
    v.x = fmaxf(fmaf(v.x, sc.x, sh.x), 0.f);
    v.y = fmaxf(fmaf(v.y, sc.y, sh.y), 0.f);
    v.z = fmaxf(fmaf(v.z, sc.z, sh.z), 0.f);
    v.w = fmaxf(fmaf(v.w, sc.w, sh.w), 0.f);
    ((float4*)out)[i] = v;
}

// ---------------- launch: fork-join (edge prep overlaps GEMM) ----------------
extern "C" void kernel_launch(void* const* d_in, const int* in_sizes, int n_in,
                              void* d_out, int out_size) {
    const float* x     = (const float*)d_in[0];
    const int*   ei    = (const int*)d_in[1];     // int32 (JAX x64 disabled)
    const float* W     = (const float*)d_in[2];
    // d_in[3] = b : cancels inside BatchNorm, unused
    const float* gamma = (const float*)d_in[4];
    const float* beta  = (const float*)d_in[5];
    float*       out   = (float*)d_out;

    const int N = in_sizes[0] / INDIM;     // 50000
    const int E = in_sizes[1] / 2;         // 600000
    const int nblk = (N + SCAN_BLK - 1) / SCAN_BLK;

    static cudaStream_t s2 = nullptr;
    static cudaEvent_t evFork = nullptr, evJoin = nullptr;
    if (s2 == nullptr) {   // first (uncaptured correctness) call only: host-side setup
        cudaFuncSetAttribute(k_gemm_mma, cudaFuncAttributeMaxDynamicSharedMemorySize, SM_GEMM);
        cudaStreamCreateWithFlags(&s2, cudaStreamNonBlocking);
        cudaEventCreateWithFlags(&evFork, cudaEventDisableTiming);
        cudaEventCreateWithFlags(&evJoin, cudaEventDisableTiming);
    }

    // main stream (default): init -> [fork] -> wsplit -> gemm -> [join] -> gather...
    k_init<<<nblk, SCAN_BLK>>>(N);
    cudaEventRecord(evFork, 0);
    cudaStreamWaitEvent(s2, evFork, 0);

    // side stream: edge prep (independent of GEMM)
    k_deg<<<((E + 3) / 4 + 255) / 256, 256, 0, s2>>>(ei, E);
    k_scan1<<<nblk, SCAN_BLK, 0, s2>>>(N);
    k_scan2<<<1, SCAN_BLK, 0, s2>>>(nblk);
    k_scan3<<<nblk, SCAN_BLK, 0, s2>>>(N);
    k_fill<<<((E + 3) / 4 + 255) / 256, 256, 0, s2>>>(ei, E);
    cudaEventRecord(evJoin, s2);

    // main stream: GEMM branch
    k_wsplit<<<HID, 256>>>(W);
    k_gemm_mma<<<(N + 127) / 128, 256, SM_GEMM>>>(x, N);

    // join, then dependent tail
    cudaStreamWaitEvent(0, evJoin, 0);
    k_gather<<<(N + 7) / 8, 256>>>(out, N);
    k_bnparam<<<1, HID>>>(N, gamma, beta);
    k_bnrelu<<<(N * 32 + 255) / 256, 256>>>(out, N * 32);
}